// round 2
// baseline (speedup 1.0000x reference)
#include <cuda_runtime.h>
#include <cuda_bf16.h>
#include <cstdint>

// ---------------------------------------------------------------------------
// Problem constants (fixed shapes: x,y = [4096,1024] fp32, scalar output)
// ---------------------------------------------------------------------------
#define BROWS 4096
#define DDIM  1024
#define EPSF  1e-6f

// exp(s/tau) = exp2(s * K2LOG), tau = 0.07
#define K2LOG 20.6099287984152302f

// GEMM tiling (sm_80-style pipelined mma.sync kernel; tcgen05 is unavailable
// because the harness compiles at compute_103 / sm_103 without the 'a' suffix)
#define BM 128
#define BN 256
#define BK 64                   // bf16 elements per K chunk
#define KT (DDIM / BK)          // 16 chunks
#define STAGES 3
#define PAD 8                   // row padding (bf16 elems) -> conflict-free ldmatrix
#define LDS_A (BK + PAD)        // 72 elems = 144 B row stride
#define STAGE_ELEMS ((BM + BN) * LDS_A)          // 27648 elems
#define SMEM_BYTES (STAGES * STAGE_ELEMS * 2)    // 165888 B

// ---------------------------------------------------------------------------
// Scratch (device globals: allocation-free rule)
// ---------------------------------------------------------------------------
__device__ __nv_bfloat16 g_xn[(size_t)BROWS * DDIM];
__device__ __nv_bfloat16 g_yn[(size_t)BROWS * DDIM];
__device__ float g_rowsum[BROWS];
__device__ float g_colsum[BROWS];
__device__ float g_diag[BROWS];

// ---------------------------------------------------------------------------
// PTX helpers (all sm_80/sm_90-safe, nothing 'a'-gated)
// ---------------------------------------------------------------------------
static __device__ __forceinline__ uint32_t smem_u32(const void* p) {
    uint32_t a;
    asm("{ .reg .u64 t; cvta.to.shared.u64 t, %1; cvt.u32.u64 %0, t; }"
        : "=r"(a) : "l"(p));
    return a;
}

static __device__ __forceinline__ float ex2f(float x) {
    float y;
    asm("ex2.approx.ftz.f32 %0, %1;" : "=f"(y) : "f"(x));
    return y;
}

static __device__ __forceinline__ void cp16(uint32_t dst, const void* src) {
    asm volatile("cp.async.cg.shared.global [%0], [%1], 16;"
                 :: "r"(dst), "l"(src) : "memory");
}
#define CP_COMMIT() asm volatile("cp.async.commit_group;" ::: "memory")
#define CP_WAIT(n)  asm volatile("cp.async.wait_group %0;" :: "n"(n) : "memory")

static __device__ __forceinline__ void ldmatrix_x4(
    uint32_t& r0, uint32_t& r1, uint32_t& r2, uint32_t& r3, uint32_t addr) {
    asm volatile("ldmatrix.sync.aligned.m8n8.x4.shared.b16 {%0,%1,%2,%3}, [%4];"
                 : "=r"(r0), "=r"(r1), "=r"(r2), "=r"(r3) : "r"(addr));
}

static __device__ __forceinline__ void mma16816(
    float* d, const uint32_t* a, const uint32_t* b) {
    asm volatile(
        "mma.sync.aligned.m16n8k16.row.col.f32.bf16.bf16.f32 "
        "{%0,%1,%2,%3}, {%4,%5,%6,%7}, {%8,%9}, {%0,%1,%2,%3};"
        : "+f"(d[0]), "+f"(d[1]), "+f"(d[2]), "+f"(d[3])
        : "r"(a[0]), "r"(a[1]), "r"(a[2]), "r"(a[3]), "r"(b[0]), "r"(b[1]));
}

// ---------------------------------------------------------------------------
// Kernel 1: normalize rows to bf16, fp32 diag S_ii, zero accumulators
// ---------------------------------------------------------------------------
__global__ void __launch_bounds__(256) norm_kernel(
    const float* __restrict__ x, const float* __restrict__ y) {
    const int i = blockIdx.x;
    const int tid = threadIdx.x;
    const float4 xv = reinterpret_cast<const float4*>(x)[(size_t)i * 256 + tid];
    const float4 yv = reinterpret_cast<const float4*>(y)[(size_t)i * 256 + tid];

    float ssx = xv.x * xv.x + xv.y * xv.y + xv.z * xv.z + xv.w * xv.w;
    float ssy = yv.x * yv.x + yv.y * yv.y + yv.z * yv.z + yv.w * yv.w;
    float sxy = xv.x * yv.x + xv.y * yv.y + xv.z * yv.z + xv.w * yv.w;
#pragma unroll
    for (int m = 16; m; m >>= 1) {
        ssx += __shfl_xor_sync(0xffffffffu, ssx, m);
        ssy += __shfl_xor_sync(0xffffffffu, ssy, m);
        sxy += __shfl_xor_sync(0xffffffffu, sxy, m);
    }
    __shared__ float s0[8], s1[8], s2[8], sc[2];
    const int wid = tid >> 5, lane = tid & 31;
    if (lane == 0) { s0[wid] = ssx; s1[wid] = ssy; s2[wid] = sxy; }
    __syncthreads();
    if (tid == 0) {
        float a = 0.f, b = 0.f, c = 0.f;
#pragma unroll
        for (int w = 0; w < 8; ++w) { a += s0[w]; b += s1[w]; c += s2[w]; }
        const float invx = 1.0f / fmaxf(sqrtf(a), EPSF);
        const float invy = 1.0f / fmaxf(sqrtf(b), EPSF);
        sc[0] = invx; sc[1] = invy;
        g_diag[i] = c * invx * invy;
        g_rowsum[i] = 0.f;
        g_colsum[i] = 0.f;
    }
    __syncthreads();
    const float invx = sc[0], invy = sc[1];
    __nv_bfloat162* ox = reinterpret_cast<__nv_bfloat162*>(g_xn + (size_t)i * DDIM);
    __nv_bfloat162* oy = reinterpret_cast<__nv_bfloat162*>(g_yn + (size_t)i * DDIM);
    ox[tid * 2]     = __floats2bfloat162_rn(xv.x * invx, xv.y * invx);
    ox[tid * 2 + 1] = __floats2bfloat162_rn(xv.z * invx, xv.w * invx);
    oy[tid * 2]     = __floats2bfloat162_rn(yv.x * invy, yv.y * invy);
    oy[tid * 2 + 1] = __floats2bfloat162_rn(yv.z * invy, yv.w * invy);
}

// ---------------------------------------------------------------------------
// Kernel 2: pipelined bf16 mma.sync GEMM tile + fused exp / row+col sums
//   grid = (BROWS/BM, BROWS/BN) = (32, 16); 512 threads, warp grid 4(m) x 4(n)
// ---------------------------------------------------------------------------
static __device__ __forceinline__ void load_stage(
    uint32_t sbase, int p, int i_base, int j_base, int tid) {
    const int s = p % STAGES;
    const uint32_t aBase = sbase + (uint32_t)(s * STAGE_ELEMS) * 2;
    const uint32_t bBase = aBase + (uint32_t)(BM * LDS_A) * 2;
    const __nv_bfloat16* gA = g_xn + (size_t)i_base * DDIM + p * BK;
    const __nv_bfloat16* gB = g_yn + (size_t)j_base * DDIM + p * BK;
    // A: 128 rows x 8 chunks(16B) = 1024 chunks, 2 per thread
#pragma unroll
    for (int r = 0; r < 2; ++r) {
        const int idx = tid + r * 512;
        const int row = idx >> 3, c = idx & 7;
        cp16(aBase + (uint32_t)(row * LDS_A + c * 8) * 2,
             gA + (size_t)row * DDIM + c * 8);
    }
    // B: 256 rows x 8 chunks = 2048 chunks, 4 per thread
#pragma unroll
    for (int r = 0; r < 4; ++r) {
        const int idx = tid + r * 512;
        const int row = idx >> 3, c = idx & 7;
        cp16(bBase + (uint32_t)(row * LDS_A + c * 8) * 2,
             gB + (size_t)row * DDIM + c * 8);
    }
    CP_COMMIT();
}

__global__ void __launch_bounds__(512, 1) gemm_exp_kernel() {
    extern __shared__ __nv_bfloat16 smem[];
    const uint32_t sbase = smem_u32(smem);
    const int tid = threadIdx.x;
    const int lane = tid & 31;
    const int wid = tid >> 5;
    const int warp_m = wid & 3;        // 0..3 -> 32-row slice
    const int warp_n = wid >> 2;       // 0..3 -> 64-col slice
    const int i_base = blockIdx.x * BM;
    const int j_base = blockIdx.y * BN;

    float acc[2][8][4];
#pragma unroll
    for (int mi = 0; mi < 2; ++mi)
#pragma unroll
        for (int ni = 0; ni < 8; ++ni)
#pragma unroll
            for (int r = 0; r < 4; ++r) acc[mi][ni][r] = 0.f;

    // prologue: fill STAGES-1 stages
    load_stage(sbase, 0, i_base, j_base, tid);
    load_stage(sbase, 1, i_base, j_base, tid);

    // lane-invariant parts of ldmatrix addressing
    const uint32_t lrow = (uint32_t)(lane & 15);
    const uint32_t koff = (uint32_t)((lane >> 4) * 8);

    for (int kt = 0; kt < KT; ++kt) {
        CP_WAIT(STAGES - 2);
        __syncthreads();
        if (kt + STAGES - 1 < KT)
            load_stage(sbase, kt + STAGES - 1, i_base, j_base, tid);

        const int s = kt % STAGES;
        const uint32_t aTile = sbase + (uint32_t)(s * STAGE_ELEMS) * 2;
        const uint32_t bTile = aTile + (uint32_t)(BM * LDS_A) * 2;
        const uint32_t aAddr0 = aTile + ((warp_m * 32 + lrow) * LDS_A + koff) * 2;
        const uint32_t bAddr0 = bTile + ((warp_n * 64 + lrow) * LDS_A + koff) * 2;

#pragma unroll
        for (int kk = 0; kk < 4; ++kk) {
            const uint32_t kb = (uint32_t)(kk * 16) * 2;
            uint32_t a[2][4];
#pragma unroll
            for (int mi = 0; mi < 2; ++mi)
                ldmatrix_x4(a[mi][0], a[mi][1], a[mi][2], a[mi][3],
                            aAddr0 + kb + (uint32_t)(mi * 16 * LDS_A) * 2);
            uint32_t b[8][2];
#pragma unroll
            for (int p = 0; p < 4; ++p) {
                uint32_t r0, r1, r2, r3;
                ldmatrix_x4(r0, r1, r2, r3,
                            bAddr0 + kb + (uint32_t)(p * 16 * LDS_A) * 2);
                b[2 * p][0] = r0; b[2 * p + 1][0] = r1;
                b[2 * p][1] = r2; b[2 * p + 1][1] = r3;
            }
#pragma unroll
            for (int mi = 0; mi < 2; ++mi)
#pragma unroll
                for (int ni = 0; ni < 8; ++ni)
                    mma16816(acc[mi][ni], a[mi], b[ni]);
        }
        __syncthreads();
    }

    // ---------------- fused epilogue: exp + row/col sums ----------------
    float rs[2][2] = {{0.f, 0.f}, {0.f, 0.f}};   // [mi][row-half]
    float cs[8][2];
#pragma unroll
    for (int ni = 0; ni < 8; ++ni) { cs[ni][0] = 0.f; cs[ni][1] = 0.f; }

#pragma unroll
    for (int mi = 0; mi < 2; ++mi)
#pragma unroll
        for (int ni = 0; ni < 8; ++ni) {
            const float e0 = ex2f(acc[mi][ni][0] * K2LOG);
            const float e1 = ex2f(acc[mi][ni][1] * K2LOG);
            const float e2 = ex2f(acc[mi][ni][2] * K2LOG);
            const float e3 = ex2f(acc[mi][ni][3] * K2LOG);
            rs[mi][0] += e0 + e1;      // row = m0 + mi*16 + gid
            rs[mi][1] += e2 + e3;      // row + 8
            cs[ni][0] += e0 + e2;      // col = n0 + ni*8 + 2*tig
            cs[ni][1] += e1 + e3;      // col + 1
        }

    const int m0 = i_base + warp_m * 32;
    const int n0 = j_base + warp_n * 64;
    const int gid = lane >> 2, tig = lane & 3;

#pragma unroll
    for (int mi = 0; mi < 2; ++mi)
#pragma unroll
        for (int h = 0; h < 2; ++h) {
            float v = rs[mi][h];
            v += __shfl_xor_sync(0xffffffffu, v, 1);
            v += __shfl_xor_sync(0xffffffffu, v, 2);
            if (tig == 0)
                atomicAdd(&g_rowsum[m0 + mi * 16 + h * 8 + gid], v);
        }
#pragma unroll
    for (int ni = 0; ni < 8; ++ni)
#pragma unroll
        for (int h = 0; h < 2; ++h) {
            float v = cs[ni][h];
            v += __shfl_xor_sync(0xffffffffu, v, 4);
            v += __shfl_xor_sync(0xffffffffu, v, 8);
            v += __shfl_xor_sync(0xffffffffu, v, 16);
            if (gid == 0)
                atomicAdd(&g_colsum[n0 + ni * 8 + 2 * tig + h], v);
        }
}

// ---------------------------------------------------------------------------
// Kernel 3: final log-reduce -> scalar loss
// ---------------------------------------------------------------------------
__global__ void __launch_bounds__(256) finalize_kernel(float* __restrict__ out) {
    const int tid = threadIdx.x;
    const double extra = (double)BROWS * 1e-6 + 1e-6;
    double acc = 0.0;
    for (int i = tid; i < BROWS; i += 256) {
        const double t = 2.0 * (double)g_diag[i] / 0.07;
        acc += t - log((double)g_rowsum[i] + extra) - log((double)g_colsum[i] + extra);
    }
    __shared__ double sb[256];
    sb[tid] = acc;
    __syncthreads();
#pragma unroll
    for (int s = 128; s; s >>= 1) {
        if (tid < s) sb[tid] += sb[tid + s];
        __syncthreads();
    }
    if (tid == 0) out[0] = (float)(sb[0] * (-1.0 / (2.0 * (double)BROWS)));
}

// ---------------------------------------------------------------------------
extern "C" void kernel_launch(void* const* d_in, const int* in_sizes, int n_in,
                              void* d_out, int out_size) {
    const float* x = (const float*)d_in[0];
    const float* y = (const float*)d_in[1];
    float* out = (float*)d_out;

    static int configured = 0;
    if (!configured) {
        cudaFuncSetAttribute(gemm_exp_kernel,
                             cudaFuncAttributeMaxDynamicSharedMemorySize, SMEM_BYTES);
        configured = 1;
    }

    norm_kernel<<<BROWS, 256>>>(x, y);
    gemm_exp_kernel<<<dim3(BROWS / BM, BROWS / BN), 512, SMEM_BYTES>>>();
    finalize_kernel<<<1, 256>>>(out);
}

// round 3
// speedup vs baseline: 1.0447x; 1.0447x over previous
#include <cuda_runtime.h>
#include <cuda_bf16.h>
#include <cuda_fp8.h>
#include <cstdint>

// ---------------------------------------------------------------------------
// Problem constants (fixed shapes: x,y = [4096,1024] fp32, scalar output)
// ---------------------------------------------------------------------------
#define BROWS 4096
#define DDIM  1024
#define EPSF  1e-6f

// Quantization pre-scale: normalized components (~N(0, 1/1024)) are scaled by
// 16 before e4m3 quantization so they sit in the normal range (not subnormal).
// The GEMM accumulator is then 256 * S, undone in the exp:
//   exp(S/tau) = exp2(acc * log2(e) / (0.07 * 256))
#define QSCALE 16.0f
#define K2LOG_S (20.6099287984152302f / 256.0f)

// GEMM tiling: fp8 e4m3 mma.sync.m16n8k32 (sm_89 path; tcgen05 is unavailable
// because the harness compiles at compute_103 / sm_103 without the 'a' suffix)
#define BM 128
#define BN 256
#define BK 128                  // fp8 elements (=bytes) per K chunk
#define KT (DDIM / BK)          // 8 chunks
#define STAGES 3
#define RS (BK + 16)            // smem row stride in bytes (pad -> conflict-free LDSM)
#define STAGE_BYTES ((BM + BN) * RS)              // 55296
#define SMEM_BYTES (STAGES * STAGE_BYTES)         // 165888

// ---------------------------------------------------------------------------
// Scratch (device globals: allocation-free rule)
// ---------------------------------------------------------------------------
__device__ uint8_t g_xq[(size_t)BROWS * DDIM];   // e4m3, row-major, K contiguous
__device__ uint8_t g_yq[(size_t)BROWS * DDIM];
__device__ float g_rowsum[BROWS];
__device__ float g_colsum[BROWS];
__device__ float g_diag[BROWS];

// ---------------------------------------------------------------------------
// PTX helpers (all <= sm_89 features; nothing 'a'-gated)
// ---------------------------------------------------------------------------
static __device__ __forceinline__ uint32_t smem_u32(const void* p) {
    uint32_t a;
    asm("{ .reg .u64 t; cvta.to.shared.u64 t, %1; cvt.u32.u64 %0, t; }"
        : "=r"(a) : "l"(p));
    return a;
}

static __device__ __forceinline__ float ex2f(float x) {
    float y;
    asm("ex2.approx.ftz.f32 %0, %1;" : "=f"(y) : "f"(x));
    return y;
}

static __device__ __forceinline__ void cp16(uint32_t dst, const void* src) {
    asm volatile("cp.async.cg.shared.global [%0], [%1], 16;"
                 :: "r"(dst), "l"(src) : "memory");
}
#define CP_COMMIT() asm volatile("cp.async.commit_group;" ::: "memory")
#define CP_WAIT(n)  asm volatile("cp.async.wait_group %0;" :: "n"(n) : "memory")

static __device__ __forceinline__ void ldmatrix_x4(
    uint32_t& r0, uint32_t& r1, uint32_t& r2, uint32_t& r3, uint32_t addr) {
    asm volatile("ldmatrix.sync.aligned.m8n8.x4.shared.b16 {%0,%1,%2,%3}, [%4];"
                 : "=r"(r0), "=r"(r1), "=r"(r2), "=r"(r3) : "r"(addr));
}

// fp8 e4m3 MMA: D(16x8,f32) += A(16x32,e4m3) * B(32x8,e4m3)
static __device__ __forceinline__ void mma16832(
    float* d, const uint32_t* a, const uint32_t* b) {
    asm volatile(
        "mma.sync.aligned.m16n8k32.row.col.f32.e4m3.e4m3.f32 "
        "{%0,%1,%2,%3}, {%4,%5,%6,%7}, {%8,%9}, {%0,%1,%2,%3};"
        : "+f"(d[0]), "+f"(d[1]), "+f"(d[2]), "+f"(d[3])
        : "r"(a[0]), "r"(a[1]), "r"(a[2]), "r"(a[3]), "r"(b[0]), "r"(b[1]));
}

static __device__ __forceinline__ uint32_t pack_fp8x4(
    float a, float b, float c, float d) {
    const __nv_fp8x2_storage_t lo =
        __nv_cvt_float2_to_fp8x2(make_float2(a, b), __NV_SATFINITE, __NV_E4M3);
    const __nv_fp8x2_storage_t hi =
        __nv_cvt_float2_to_fp8x2(make_float2(c, d), __NV_SATFINITE, __NV_E4M3);
    return (uint32_t)lo | ((uint32_t)hi << 16);
}

// ---------------------------------------------------------------------------
// Kernel 1: warp-per-row normalize -> e4m3 (scaled by 16), fp32 diag, zeroing
//   256 threads = 8 warps = 8 rows per block; grid = 512
// ---------------------------------------------------------------------------
__global__ void __launch_bounds__(256) norm_kernel(
    const float* __restrict__ x, const float* __restrict__ y) {
    const int lane = threadIdx.x & 31;
    const int row = blockIdx.x * 8 + (threadIdx.x >> 5);

    // lane covers columns [32*lane, 32*lane+32): 8 float4 from each input
    const float4* xr = reinterpret_cast<const float4*>(x) + (size_t)row * 256 + lane * 8;
    const float4* yr = reinterpret_cast<const float4*>(y) + (size_t)row * 256 + lane * 8;
    float4 xv[8], yv[8];
#pragma unroll
    for (int u = 0; u < 8; ++u) xv[u] = xr[u];
#pragma unroll
    for (int u = 0; u < 8; ++u) yv[u] = yr[u];

    float ssx = 0.f, ssy = 0.f, sxy = 0.f;
#pragma unroll
    for (int u = 0; u < 8; ++u) {
        ssx += xv[u].x * xv[u].x + xv[u].y * xv[u].y + xv[u].z * xv[u].z + xv[u].w * xv[u].w;
        ssy += yv[u].x * yv[u].x + yv[u].y * yv[u].y + yv[u].z * yv[u].z + yv[u].w * yv[u].w;
        sxy += xv[u].x * yv[u].x + xv[u].y * yv[u].y + xv[u].z * yv[u].z + xv[u].w * yv[u].w;
    }
#pragma unroll
    for (int m = 16; m; m >>= 1) {
        ssx += __shfl_xor_sync(0xffffffffu, ssx, m);
        ssy += __shfl_xor_sync(0xffffffffu, ssy, m);
        sxy += __shfl_xor_sync(0xffffffffu, sxy, m);
    }
    const float invx = 1.0f / fmaxf(sqrtf(ssx), EPSF);
    const float invy = 1.0f / fmaxf(sqrtf(ssy), EPSF);
    if (lane == 0) {
        g_diag[row] = sxy * invx * invy;
        g_rowsum[row] = 0.f;
        g_colsum[row] = 0.f;
    }
    const float qx = QSCALE * invx, qy = QSCALE * invy;

    uint32_t px[8], py[8];
#pragma unroll
    for (int u = 0; u < 8; ++u) {
        px[u] = pack_fp8x4(xv[u].x * qx, xv[u].y * qx, xv[u].z * qx, xv[u].w * qx);
        py[u] = pack_fp8x4(yv[u].x * qy, yv[u].y * qy, yv[u].z * qy, yv[u].w * qy);
    }
    uint4* ox = reinterpret_cast<uint4*>(g_xq + (size_t)row * DDIM + lane * 32);
    uint4* oy = reinterpret_cast<uint4*>(g_yq + (size_t)row * DDIM + lane * 32);
    ox[0] = make_uint4(px[0], px[1], px[2], px[3]);
    ox[1] = make_uint4(px[4], px[5], px[6], px[7]);
    oy[0] = make_uint4(py[0], py[1], py[2], py[3]);
    oy[1] = make_uint4(py[4], py[5], py[6], py[7]);
}

// ---------------------------------------------------------------------------
// Kernel 2: pipelined fp8 mma.sync GEMM tile + fused exp / row+col sums
//   grid = (32, 16); 512 threads, warp grid 4(m) x 4(n), warp tile 32x64
// ---------------------------------------------------------------------------
static __device__ __forceinline__ void load_stage(
    uint32_t sbase, int p, int i_base, int j_base, int tid) {
    const int s = p % STAGES;
    const uint32_t aBase = sbase + (uint32_t)(s * STAGE_BYTES);
    const uint32_t bBase = aBase + (uint32_t)(BM * RS);
    const uint8_t* gA = g_xq + (size_t)i_base * DDIM + p * BK;
    const uint8_t* gB = g_yq + (size_t)j_base * DDIM + p * BK;
    // A: 128 rows x 8 chunks(16B) = 1024 chunks, 2 per thread
#pragma unroll
    for (int r = 0; r < 2; ++r) {
        const int idx = tid + r * 512;
        const int row = idx >> 3, c = idx & 7;
        cp16(aBase + (uint32_t)(row * RS + c * 16), gA + (size_t)row * DDIM + c * 16);
    }
    // B: 256 rows x 8 chunks = 2048 chunks, 4 per thread
#pragma unroll
    for (int r = 0; r < 4; ++r) {
        const int idx = tid + r * 512;
        const int row = idx >> 3, c = idx & 7;
        cp16(bBase + (uint32_t)(row * RS + c * 16), gB + (size_t)row * DDIM + c * 16);
    }
    CP_COMMIT();
}

__global__ void __launch_bounds__(512, 1) gemm_exp_kernel() {
    extern __shared__ uint8_t smem[];
    const uint32_t sbase = smem_u32(smem);
    const int tid = threadIdx.x;
    const int lane = tid & 31;
    const int wid = tid >> 5;
    const int warp_m = wid & 3;        // 0..3 -> 32-row slice
    const int warp_n = wid >> 2;       // 0..3 -> 64-col slice
    const int i_base = blockIdx.x * BM;
    const int j_base = blockIdx.y * BN;

    float acc[2][8][4];
#pragma unroll
    for (int mi = 0; mi < 2; ++mi)
#pragma unroll
        for (int ni = 0; ni < 8; ++ni)
#pragma unroll
            for (int r = 0; r < 4; ++r) acc[mi][ni][r] = 0.f;

    load_stage(sbase, 0, i_base, j_base, tid);
    load_stage(sbase, 1, i_base, j_base, tid);

    // ldmatrix addressing: 16 rows x 32B; lanes 0-15 pick rows, 16-31 add 16B
    const uint32_t lrow = (uint32_t)(lane & 15);
    const uint32_t koff = (uint32_t)((lane >> 4) * 16);

    for (int kt = 0; kt < KT; ++kt) {
        CP_WAIT(STAGES - 2);
        __syncthreads();
        if (kt + STAGES - 1 < KT)
            load_stage(sbase, kt + STAGES - 1, i_base, j_base, tid);

        const int s = kt % STAGES;
        const uint32_t aTile = sbase + (uint32_t)(s * STAGE_BYTES);
        const uint32_t bTile = aTile + (uint32_t)(BM * RS);
        const uint32_t aAddr0 = aTile + (warp_m * 32 + lrow) * RS + koff;
        const uint32_t bAddr0 = bTile + (warp_n * 64 + lrow) * RS + koff;

#pragma unroll
        for (int kk = 0; kk < 4; ++kk) {          // 4 x k32 = BK
            const uint32_t kb = (uint32_t)(kk * 32);
            uint32_t a[2][4];
#pragma unroll
            for (int mi = 0; mi < 2; ++mi)
                ldmatrix_x4(a[mi][0], a[mi][1], a[mi][2], a[mi][3],
                            aAddr0 + kb + (uint32_t)(mi * 16 * RS));
            uint32_t b[8][2];
#pragma unroll
            for (int p = 0; p < 4; ++p) {
                uint32_t r0, r1, r2, r3;
                ldmatrix_x4(r0, r1, r2, r3, bAddr0 + kb + (uint32_t)(p * 16 * RS));
                b[2 * p][0] = r0; b[2 * p + 1][0] = r1;
                b[2 * p][1] = r2; b[2 * p + 1][1] = r3;
            }
#pragma unroll
            for (int mi = 0; mi < 2; ++mi)
#pragma unroll
                for (int ni = 0; ni < 8; ++ni)
                    mma16832(acc[mi][ni], a[mi], b[ni]);
        }
        __syncthreads();
    }

    // ---------------- fused epilogue: exp + row/col sums ----------------
    float rs[2][2] = {{0.f, 0.f}, {0.f, 0.f}};   // [mi][row-half]
    float cs[8][2];
#pragma unroll
    for (int ni = 0; ni < 8; ++ni) { cs[ni][0] = 0.f; cs[ni][1] = 0.f; }

#pragma unroll
    for (int mi = 0; mi < 2; ++mi)
#pragma unroll
        for (int ni = 0; ni < 8; ++ni) {
            const float e0 = ex2f(acc[mi][ni][0] * K2LOG_S);
            const float e1 = ex2f(acc[mi][ni][1] * K2LOG_S);
            const float e2 = ex2f(acc[mi][ni][2] * K2LOG_S);
            const float e3 = ex2f(acc[mi][ni][3] * K2LOG_S);
            rs[mi][0] += e0 + e1;      // row = m0 + mi*16 + gid
            rs[mi][1] += e2 + e3;      // row + 8
            cs[ni][0] += e0 + e2;      // col = n0 + ni*8 + 2*tig
            cs[ni][1] += e1 + e3;      // col + 1
        }

    const int m0 = i_base + warp_m * 32;
    const int n0 = j_base + warp_n * 64;
    const int gid = lane >> 2, tig = lane & 3;

#pragma unroll
    for (int mi = 0; mi < 2; ++mi)
#pragma unroll
        for (int h = 0; h < 2; ++h) {
            float v = rs[mi][h];
            v += __shfl_xor_sync(0xffffffffu, v, 1);
            v += __shfl_xor_sync(0xffffffffu, v, 2);
            if (tig == 0)
                atomicAdd(&g_rowsum[m0 + mi * 16 + h * 8 + gid], v);
        }
#pragma unroll
    for (int ni = 0; ni < 8; ++ni)
#pragma unroll
        for (int h = 0; h < 2; ++h) {
            float v = cs[ni][h];
            v += __shfl_xor_sync(0xffffffffu, v, 4);
            v += __shfl_xor_sync(0xffffffffu, v, 8);
            v += __shfl_xor_sync(0xffffffffu, v, 16);
            if (gid == 0)
                atomicAdd(&g_colsum[n0 + ni * 8 + 2 * tig + h], v);
        }
}

// ---------------------------------------------------------------------------
// Kernel 3: final log-reduce -> scalar loss
// ---------------------------------------------------------------------------
__global__ void __launch_bounds__(256) finalize_kernel(float* __restrict__ out) {
    const int tid = threadIdx.x;
    const double extra = (double)BROWS * 1e-6 + 1e-6;
    double acc = 0.0;
    for (int i = tid; i < BROWS; i += 256) {
        const double t = 2.0 * (double)g_diag[i] / 0.07;
        acc += t - log((double)g_rowsum[i] + extra) - log((double)g_colsum[i] + extra);
    }
    __shared__ double sb[256];
    sb[tid] = acc;
    __syncthreads();
#pragma unroll
    for (int s = 128; s; s >>= 1) {
        if (tid < s) sb[tid] += sb[tid + s];
        __syncthreads();
    }
    if (tid == 0) out[0] = (float)(sb[0] * (-1.0 / (2.0 * (double)BROWS)));
}

// ---------------------------------------------------------------------------
extern "C" void kernel_launch(void* const* d_in, const int* in_sizes, int n_in,
                              void* d_out, int out_size) {
    const float* x = (const float*)d_in[0];
    const float* y = (const float*)d_in[1];
    float* out = (float*)d_out;

    static int configured = 0;
    if (!configured) {
        cudaFuncSetAttribute(gemm_exp_kernel,
                             cudaFuncAttributeMaxDynamicSharedMemorySize, SMEM_BYTES);
        configured = 1;
    }

    norm_kernel<<<BROWS / 8, 256>>>(x, y);
    gemm_exp_kernel<<<dim3(BROWS / BM, BROWS / BN), 512, SMEM_BYTES>>>();
    finalize_kernel<<<1, 256>>>(out);
}